// round 1
// baseline (speedup 1.0000x reference)
#include <cuda_runtime.h>
#include <math.h>

#define BSZ   4096
#define NND   32
#define ZDIM  128
#define HID   256
#define INF   64
#define TB    32
#define NTHR  256
#define NCTA  (BSZ / TB)

#define ZST   129   // padded stride for z tile (odd -> conflict-free per-sample access)
#define GST   65    // padded stride for dV/dr tile
#define SST   129   // padded stride for output stage

// transposed weights (device scratch; rebuilt every launch, deterministic)
__device__ float g_W1T[HID * HID];
__device__ float g_W2T[HID * HID];
__device__ float g_W0T[HID * INF];

__global__ void transpose_k(const float* __restrict__ W0,
                            const float* __restrict__ W1,
                            const float* __restrict__ W2)
{
    int i = blockIdx.x * blockDim.x + threadIdx.x;
    if (i < HID * HID) {
        int r = i >> 8;      // source row (k)
        int c = i & 255;     // source col (j)
        g_W1T[c * HID + r] = W1[i];
        g_W2T[c * HID + r] = W2[i];
        if (r < INF) g_W0T[c * INF + r] = W0[i];
    }
}

// acc[i][j] += sum_k in[(s0+i)*istride + k] * W[k*256 + fidx + 64*j]
__device__ __forceinline__ void mm4(float acc[8][4],
                                    const float* in, int istride,
                                    const float* __restrict__ W, int K,
                                    int fidx, int s0)
{
    #pragma unroll 4
    for (int k = 0; k < K; k++) {
        float w0 = W[k * HID + fidx];
        float w1 = W[k * HID + fidx + 64];
        float w2 = W[k * HID + fidx + 128];
        float w3 = W[k * HID + fidx + 192];
        const float* hp = in + s0 * istride + k;
        #pragma unroll
        for (int i = 0; i < 8; i++) {
            float h = hp[i * istride];
            acc[i][0] = fmaf(h, w0, acc[i][0]);
            acc[i][1] = fmaf(h, w1, acc[i][1]);
            acc[i][2] = fmaf(h, w2, acc[i][2]);
            acc[i][3] = fmaf(h, w3, acc[i][3]);
        }
    }
}

__global__ __launch_bounds__(NTHR, 1)
void chnn_kernel(const float* __restrict__ z,
                 const float* __restrict__ m_params,
                 const float* __restrict__ W0, const float* __restrict__ b0,
                 const float* __restrict__ W1, const float* __restrict__ b1,
                 const float* __restrict__ W2, const float* __restrict__ b2,
                 const float* __restrict__ W3,
                 float* __restrict__ out)
{
    extern __shared__ float sm[];
    float* zbuf = sm;                       // TB*ZST  = 4128
    float* bufA = zbuf + TB * ZST;          // TB*HID  = 8192
    float* bufB = bufA + TB * HID;          // 8192
    float* sig0 = bufB + TB * HID;          // 8192
    float* sig1 = sig0 + TB * HID;          // 8192
    float* gbuf = sig1 + TB * HID;          // TB*GST  = 2080
    float* invm = gbuf + TB * GST;          // 32

    const int tid  = threadIdx.x;
    const int blk  = blockIdx.x;
    const int fidx = tid & 63;
    const int sg   = tid >> 6;
    const int s0   = sg * 8;

    // cooperative load of z tile (padded rows)
    const float* zg = z + (size_t)blk * TB * ZDIM;
    for (int i = tid; i < TB * ZDIM; i += NTHR)
        zbuf[(i >> 7) * ZST + (i & 127)] = zg[i];
    if (tid < NND) invm[tid] = expf(-m_params[tid]);
    __syncthreads();

    float acc[8][4];

    // ============ L0: a0 = r @ W0 + b0 ; h0 -> bufA, sig0 ============
    {
        #pragma unroll
        for (int j = 0; j < 4; j++) {
            float bv = b0[fidx + 64 * j];
            #pragma unroll
            for (int i = 0; i < 8; i++) acc[i][j] = bv;
        }
        mm4(acc, zbuf, ZST, W0, INF, fidx, s0);
        #pragma unroll
        for (int i = 0; i < 8; i++) {
            #pragma unroll
            for (int j = 0; j < 4; j++) {
                float a = acc[i][j];
                float e = expf(-fabsf(a));
                float t = 1.0f / (1.0f + e);
                int o = (s0 + i) * HID + fidx + 64 * j;
                bufA[o] = fmaxf(a, 0.f) + log1pf(e);
                sig0[o] = (a >= 0.f) ? t : e * t;
            }
        }
    }
    __syncthreads();

    // ============ L1: h1 -> bufB, sig1 ============
    {
        #pragma unroll
        for (int j = 0; j < 4; j++) {
            float bv = b1[fidx + 64 * j];
            #pragma unroll
            for (int i = 0; i < 8; i++) acc[i][j] = bv;
        }
        mm4(acc, bufA, HID, W1, HID, fidx, s0);
        #pragma unroll
        for (int i = 0; i < 8; i++) {
            #pragma unroll
            for (int j = 0; j < 4; j++) {
                float a = acc[i][j];
                float e = expf(-fabsf(a));
                float t = 1.0f / (1.0f + e);
                int o = (s0 + i) * HID + fidx + 64 * j;
                bufB[o] = fmaxf(a, 0.f) + log1pf(e);
                sig1[o] = (a >= 0.f) ? t : e * t;
            }
        }
    }
    __syncthreads();

    // ============ L2 fused with da2 = W3[f]*sigmoid(a2) -> bufA ============
    {
        #pragma unroll
        for (int j = 0; j < 4; j++) {
            float bv = b2[fidx + 64 * j];
            #pragma unroll
            for (int i = 0; i < 8; i++) acc[i][j] = bv;
        }
        mm4(acc, bufB, HID, W2, HID, fidx, s0);
        #pragma unroll
        for (int j = 0; j < 4; j++) {
            float w3v = W3[fidx + 64 * j];
            #pragma unroll
            for (int i = 0; i < 8; i++) {
                float a = acc[i][j];
                float e = expf(-fabsf(a));
                float t = 1.0f / (1.0f + e);
                float sgv = (a >= 0.f) ? t : e * t;
                bufA[(s0 + i) * HID + fidx + 64 * j] = w3v * sgv;
            }
        }
    }
    __syncthreads();

    // ============ B1: dh1 = da2 @ W2^T ; da1 = dh1*sig1 -> bufB ============
    {
        #pragma unroll
        for (int j = 0; j < 4; j++)
            #pragma unroll
            for (int i = 0; i < 8; i++) acc[i][j] = 0.f;
        mm4(acc, bufA, HID, g_W2T, HID, fidx, s0);
        #pragma unroll
        for (int i = 0; i < 8; i++)
            #pragma unroll
            for (int j = 0; j < 4; j++) {
                int o = (s0 + i) * HID + fidx + 64 * j;
                bufB[o] = acc[i][j] * sig1[o];
            }
    }
    __syncthreads();

    // ============ B2: dh0 = da1 @ W1^T ; da0 = dh0*sig0 -> bufA ============
    {
        #pragma unroll
        for (int j = 0; j < 4; j++)
            #pragma unroll
            for (int i = 0; i < 8; i++) acc[i][j] = 0.f;
        mm4(acc, bufB, HID, g_W1T, HID, fidx, s0);
        #pragma unroll
        for (int i = 0; i < 8; i++)
            #pragma unroll
            for (int j = 0; j < 4; j++) {
                int o = (s0 + i) * HID + fidx + 64 * j;
                bufA[o] = acc[i][j] * sig0[o];
            }
    }
    __syncthreads();

    // ============ B3: g = dV/dr = da0 @ W0^T (256 -> 64) -> gbuf ============
    {
        float a8[8];
        #pragma unroll
        for (int i = 0; i < 8; i++) a8[i] = 0.f;
        const int m = fidx;
        #pragma unroll 4
        for (int k = 0; k < HID; k++) {
            float w = g_W0T[k * INF + m];
            #pragma unroll
            for (int i = 0; i < 8; i++)
                a8[i] = fmaf(bufA[(s0 + i) * HID + k], w, a8[i]);
        }
        #pragma unroll
        for (int i = 0; i < 8; i++) gbuf[(s0 + i) * GST + m] = a8[i];
    }
    __syncthreads();

    // ============ constraint solve: 1 thread / sample ============
    // A = [[0,G],[-G,S]] with G = E^T M^-1 E tridiagonal SPD (32x32),
    // S = B - B^T tridiagonal antisymmetric. Two Thomas solves.
    float* scr = sig0;  // sig0+sig1 (16384 floats) free now
    float* Ex  = scr + 0  * NND * TB;
    float* Ey  = scr + 1  * NND * TB;
    float* Edx = scr + 2  * NND * TB;
    float* Edy = scr + 3  * NND * TB;
    float* Vx  = scr + 4  * NND * TB;
    float* Vy  = scr + 5  * NND * TB;
    float* Dd  = scr + 6  * NND * TB;
    float* Du  = scr + 7  * NND * TB;
    float* Dl  = scr + 8  * NND * TB;
    float* So  = scr + 9  * NND * TB;
    float* R0  = scr + 10 * NND * TB;   // b0 -> x1
    float* R1  = scr + 11 * NND * TB;   // b1 -> y -> x0

    if (tid < TB) {
        const int s = tid;
        const float* zr = zbuf + s * ZST;

        // build E_c, Edot_c, v  (E_0 = 2 r_0; E_c = 2(r_{c-1}-r_c))
        {
            float prx = zr[0], pry = zr[1];
            float im  = invm[0];
            float pvx = zr[64] * im, pvy = zr[65] * im;
            Ex[s]  = 2.f * prx;  Ey[s]  = 2.f * pry;
            Edx[s] = 2.f * pvx;  Edy[s] = 2.f * pvy;
            Vx[s] = pvx; Vy[s] = pvy;
            for (int c = 1; c < NND; c++) {
                float rx = zr[2*c], ry = zr[2*c+1];
                float imc = invm[c];
                float vx = zr[64 + 2*c] * imc, vy = zr[65 + 2*c] * imc;
                Ex[c*TB+s]  = 2.f*(prx - rx);  Ey[c*TB+s]  = 2.f*(pry - ry);
                Edx[c*TB+s] = 2.f*(pvx - vx);  Edy[c*TB+s] = 2.f*(pvy - vy);
                Vx[c*TB+s] = vx; Vy[c*TB+s] = vy;
                prx = rx; pry = ry; pvx = vx; pvy = vy;
            }
        }
        // tridiagonal G (Dd diag, Du upper), S offdiag (So), rhs b0 (R0), b1 (R1)
        {
            float e0x = Ex[s],  e0y = Ey[s];
            float d0x = Edx[s], d0y = Edy[s];
            float v0x = Vx[s],  v0y = Vy[s];
            float im0 = invm[0];
            float e1x = Ex[TB+s],  e1y = Ey[TB+s];
            float d1x = Edx[TB+s], d1y = Edy[TB+s];
            Dd[s] = im0 * (e0x*e0x + e0y*e0y);
            Du[s] = im0 * (e0x*e1x + e0y*e1y);
            So[s] = im0 * (d0x*e1x + d0y*e1y - d1x*e0x - d1y*e0y);
            R0[s] = e0x*v0x + e0y*v0y;
            float g0x = gbuf[s*GST + 0], g0y = gbuf[s*GST + 1];
            R1[s] = d0x*v0x + d0y*v0y - im0*(e0x*g0x + e0y*g0y);
            for (int c = 1; c < NND; c++) {
                float ecx = Ex[c*TB+s],  ecy = Ey[c*TB+s];
                float dcx = Edx[c*TB+s], dcy = Edy[c*TB+s];
                float imc = invm[c], imp = invm[c-1];
                Dd[c*TB+s] = (imp + imc) * (ecx*ecx + ecy*ecy);
                R0[c*TB+s] = 0.5f * (ecx*dcx + ecy*dcy);
                float gpx = gbuf[s*GST + 2*(c-1)], gpy = gbuf[s*GST + 2*(c-1)+1];
                float gcx = gbuf[s*GST + 2*c],     gcy = gbuf[s*GST + 2*c+1];
                R1[c*TB+s] = 0.5f*(dcx*dcx + dcy*dcy)
                           - (ecx*(imp*gpx - imc*gcx) + ecy*(imp*gpy - imc*gcy));
                if (c < NND - 1) {
                    float enx = Ex[(c+1)*TB+s],  eny = Ey[(c+1)*TB+s];
                    float dnx = Edx[(c+1)*TB+s], dny = Edy[(c+1)*TB+s];
                    Du[c*TB+s] = -imc * (ecx*enx + ecy*eny);
                    So[c*TB+s] =  imc * (dnx*ecx + dny*ecy - dcx*enx - dcy*eny);
                }
            }
        }
        // Thomas factorization of G
        for (int c = 1; c < NND; c++) {
            float l = Du[(c-1)*TB+s] / Dd[(c-1)*TB+s];
            Dl[c*TB+s] = l;
            Dd[c*TB+s] = Dd[c*TB+s] - l * Du[(c-1)*TB+s];
        }
        // solve G x1 = b0 (in place in R0)
        for (int c = 1; c < NND; c++)
            R0[c*TB+s] -= Dl[c*TB+s] * R0[(c-1)*TB+s];
        R0[(NND-1)*TB+s] /= Dd[(NND-1)*TB+s];
        for (int c = NND - 2; c >= 0; c--)
            R0[c*TB+s] = (R0[c*TB+s] - Du[c*TB+s] * R0[(c+1)*TB+s]) / Dd[c*TB+s];
        // y = S x1 - b1 (into R1)
        R1[s] = So[s] * R0[TB+s] - R1[s];
        for (int c = 1; c < NND - 1; c++)
            R1[c*TB+s] = So[c*TB+s]*R0[(c+1)*TB+s] - So[(c-1)*TB+s]*R0[(c-1)*TB+s] - R1[c*TB+s];
        R1[(NND-1)*TB+s] = -So[(NND-2)*TB+s]*R0[(NND-2)*TB+s] - R1[(NND-1)*TB+s];
        // solve G x0 = y (in place in R1)
        for (int c = 1; c < NND; c++)
            R1[c*TB+s] -= Dl[c*TB+s] * R1[(c-1)*TB+s];
        R1[(NND-1)*TB+s] /= Dd[(NND-1)*TB+s];
        for (int c = NND - 2; c >= 0; c--)
            R1[c*TB+s] = (R1[c*TB+s] - Du[c*TB+s]*R1[(c+1)*TB+s]) / Dd[c*TB+s];

        // output: out_r = v - M^-1 (E x1);  out_p = -g + (E x0) + (Edot x1)
        float* st = bufB + s * SST;
        for (int i = 0; i < NND; i++) {
            float eix = Ex[i*TB+s],  eiy = Ey[i*TB+s];
            float dix = Edx[i*TB+s], diy = Edy[i*TB+s];
            float x1i = R0[i*TB+s],  x0i = R1[i*TB+s];
            float p1x, p1y, p0x, p0y, pdx, pdy;
            if (i == 0) {
                float enx = Ex[TB+s],  eny = Ey[TB+s];
                float dnx = Edx[TB+s], dny = Edy[TB+s];
                float x1n = R0[TB+s],  x0n = R1[TB+s];
                p1x = eix*x1i + enx*x1n;  p1y = eiy*x1i + eny*x1n;
                p0x = eix*x0i + enx*x0n;  p0y = eiy*x0i + eny*x0n;
                pdx = dix*x1i + dnx*x1n;  pdy = diy*x1i + dny*x1n;
            } else if (i < NND - 1) {
                float enx = Ex[(i+1)*TB+s],  eny = Ey[(i+1)*TB+s];
                float dnx = Edx[(i+1)*TB+s], dny = Edy[(i+1)*TB+s];
                float x1n = R0[(i+1)*TB+s],  x0n = R1[(i+1)*TB+s];
                p1x = -eix*x1i + enx*x1n;  p1y = -eiy*x1i + eny*x1n;
                p0x = -eix*x0i + enx*x0n;  p0y = -eiy*x0i + eny*x0n;
                pdx = -dix*x1i + dnx*x1n;  pdy = -diy*x1i + dny*x1n;
            } else {
                p1x = -eix*x1i; p1y = -eiy*x1i;
                p0x = -eix*x0i; p0y = -eiy*x0i;
                pdx = -dix*x1i; pdy = -diy*x1i;
            }
            float imi = invm[i];
            st[2*i]     = Vx[i*TB+s] - imi * p1x;
            st[2*i + 1] = Vy[i*TB+s] - imi * p1y;
            float gx = gbuf[s*GST + 2*i], gy = gbuf[s*GST + 2*i + 1];
            st[64 + 2*i]     = -gx + p0x + pdx;
            st[64 + 2*i + 1] = -gy + p0y + pdy;
        }
    }
    __syncthreads();

    // coalesced store of staged output
    float* outg = out + (size_t)blk * TB * ZDIM;
    for (int i = tid; i < TB * ZDIM; i += NTHR)
        outg[i] = bufB[(i >> 7) * SST + (i & 127)];
}

extern "C" void kernel_launch(void* const* d_in, const int* in_sizes, int n_in,
                              void* d_out, int out_size)
{
    (void)in_sizes; (void)n_in; (void)out_size;
    const float* z  = (const float*)d_in[1];
    const float* mp = (const float*)d_in[2];
    const float* W0 = (const float*)d_in[3];
    const float* b0 = (const float*)d_in[4];
    const float* W1 = (const float*)d_in[5];
    const float* b1 = (const float*)d_in[6];
    const float* W2 = (const float*)d_in[7];
    const float* b2 = (const float*)d_in[8];
    const float* W3 = (const float*)d_in[9];
    float* out = (float*)d_out;

    transpose_k<<<(HID * HID + 255) / 256, 256>>>(W0, W1, W2);

    size_t smem = (size_t)(TB * ZST + 4 * TB * HID + TB * GST + 32) * sizeof(float);
    cudaFuncSetAttribute(chnn_kernel, cudaFuncAttributeMaxDynamicSharedMemorySize, (int)smem);
    chnn_kernel<<<NCTA, NTHR, smem>>>(z, mp, W0, b0, W1, b1, W2, b2, W3, out);
}

// round 2
// speedup vs baseline: 1.4552x; 1.4552x over previous
#include <cuda_runtime.h>
#include <math.h>

#define BSZ   4096
#define NND   32
#define ZDIM  128
#define HID   256
#define INF   64
#define TB    32
#define NTHR  512
#define NCTA  (BSZ / TB)

#define ZST   132   // padded stride for z tile (132*4B = 33*16B -> float4-aligned rows)
#define GST   65    // padded stride for dV/dr tile
#define SST   129   // padded stride for output stage

typedef unsigned long long ull;

// transposed weights (device scratch; rebuilt every launch, deterministic)
__device__ __align__(16) float g_W1T[HID * HID];
__device__ __align__(16) float g_W2T[HID * HID];
__device__ __align__(16) float g_W0T[HID * INF];

__global__ void transpose_k(const float* __restrict__ W0,
                            const float* __restrict__ W1,
                            const float* __restrict__ W2)
{
    int i = blockIdx.x * blockDim.x + threadIdx.x;
    if (i < HID * HID) {
        int r = i >> 8;      // source row (k)
        int c = i & 255;     // source col (j)
        g_W1T[c * HID + r] = W1[i];
        g_W2T[c * HID + r] = W2[i];
        if (r < INF) g_W0T[c * INF + r] = W0[i];
    }
}

// ---- packed f32x2 helpers (sm_103a) ----
__device__ __forceinline__ ull pk2(float x) {
    ull d; asm("mov.b64 %0, {%1, %1};" : "=l"(d) : "f"(x)); return d;
}
__device__ __forceinline__ ull ff2(ull a, ull b, ull c) {
    ull d; asm("fma.rn.f32x2 %0, %1, %2, %3;" : "=l"(d) : "l"(a), "l"(b), "l"(c)); return d;
}
__device__ __forceinline__ float2 upk(ull a) {
    float2 r; asm("mov.b64 {%0, %1}, %2;" : "=f"(r.x), "=f"(r.y) : "l"(a)); return r;
}
__device__ __forceinline__ float fcomp(const float4& v, int kk) {
    switch (kk) { case 0: return v.x; case 1: return v.y; case 2: return v.z; default: return v.w; }
}

// acc[i][jp] (+)= sum_k in[(s0+i)*istride + k] * W[k*256 + f4 + 2*jp + {0,1}]
// W rows contiguous in the 4 features per thread -> LDG.128, lanes contiguous 512B.
// in read as float4 over k (broadcast within warp).
__device__ __forceinline__ void mmv(ull acc[4][2],
                                    const float* in, int istride,
                                    const float* __restrict__ W, int K,
                                    int f4, int s0)
{
    #pragma unroll 2
    for (int k4 = 0; k4 < K; k4 += 4) {
        float4 h[4];
        #pragma unroll
        for (int i = 0; i < 4; i++)
            h[i] = *(const float4*)(in + (s0 + i) * istride + k4);
        #pragma unroll
        for (int kk = 0; kk < 4; kk++) {
            const ulonglong2 wv = *(const ulonglong2*)(W + (k4 + kk) * HID + f4);
            #pragma unroll
            for (int i = 0; i < 4; i++) {
                ull hd = pk2(fcomp(h[i], kk));
                acc[i][0] = ff2(hd, wv.x, acc[i][0]);
                acc[i][1] = ff2(hd, wv.y, acc[i][1]);
            }
        }
    }
}

__global__ __launch_bounds__(NTHR, 1)
void chnn_kernel(const float* __restrict__ z,
                 const float* __restrict__ m_params,
                 const float* __restrict__ W0, const float* __restrict__ b0,
                 const float* __restrict__ W1, const float* __restrict__ b1,
                 const float* __restrict__ W2, const float* __restrict__ b2,
                 const float* __restrict__ W3,
                 float* __restrict__ out)
{
    extern __shared__ float sm[];
    float* zbuf = sm;                       // TB*ZST  = 4224
    float* bufA = zbuf + TB * ZST;          // TB*HID  = 8192
    float* bufB = bufA + TB * HID;          // 8192
    float* sig0 = bufB + TB * HID;          // 8192
    float* sig1 = sig0 + TB * HID;          // 8192
    float* gbuf = sig1 + TB * HID;          // TB*GST  = 2080
    float* invm = gbuf + TB * GST;          // 32

    const int tid  = threadIdx.x;
    const int blk  = blockIdx.x;
    const int f4   = (tid & 63) * 4;        // 4 consecutive features per thread
    const int s0   = (tid >> 6) * 4;        // 4 samples per thread (8 groups)

    // cooperative load of z tile (padded rows)
    const float* zg = z + (size_t)blk * TB * ZDIM;
    for (int i = tid; i < TB * ZDIM; i += NTHR)
        zbuf[(i >> 7) * ZST + (i & 127)] = zg[i];
    if (tid < NND) invm[tid] = expf(-m_params[tid]);
    __syncthreads();

    ull acc[4][2];

    // ============ L0: a0 = r @ W0 + b0 ; h0 -> bufA, sig0 ============
    {
        const ulonglong2 bv = *(const ulonglong2*)(b0 + f4);
        #pragma unroll
        for (int i = 0; i < 4; i++) { acc[i][0] = bv.x; acc[i][1] = bv.y; }
        mmv(acc, zbuf, ZST, W0, INF, f4, s0);
        #pragma unroll
        for (int i = 0; i < 4; i++) {
            float2 a01 = upk(acc[i][0]), a23 = upk(acc[i][1]);
            float av[4] = {a01.x, a01.y, a23.x, a23.y};
            float hb[4], sb[4];
            #pragma unroll
            for (int j = 0; j < 4; j++) {
                float a = av[j];
                float e = expf(-fabsf(a));
                float t = 1.0f / (1.0f + e);
                hb[j] = fmaxf(a, 0.f) + log1pf(e);
                sb[j] = (a >= 0.f) ? t : e * t;
            }
            int o = (s0 + i) * HID + f4;
            *(float4*)(bufA + o) = make_float4(hb[0], hb[1], hb[2], hb[3]);
            *(float4*)(sig0 + o) = make_float4(sb[0], sb[1], sb[2], sb[3]);
        }
    }
    __syncthreads();

    // ============ L1: h1 -> bufB, sig1 ============
    {
        const ulonglong2 bv = *(const ulonglong2*)(b1 + f4);
        #pragma unroll
        for (int i = 0; i < 4; i++) { acc[i][0] = bv.x; acc[i][1] = bv.y; }
        mmv(acc, bufA, HID, W1, HID, f4, s0);
        #pragma unroll
        for (int i = 0; i < 4; i++) {
            float2 a01 = upk(acc[i][0]), a23 = upk(acc[i][1]);
            float av[4] = {a01.x, a01.y, a23.x, a23.y};
            float hb[4], sb[4];
            #pragma unroll
            for (int j = 0; j < 4; j++) {
                float a = av[j];
                float e = expf(-fabsf(a));
                float t = 1.0f / (1.0f + e);
                hb[j] = fmaxf(a, 0.f) + log1pf(e);
                sb[j] = (a >= 0.f) ? t : e * t;
            }
            int o = (s0 + i) * HID + f4;
            *(float4*)(bufB + o) = make_float4(hb[0], hb[1], hb[2], hb[3]);
            *(float4*)(sig1 + o) = make_float4(sb[0], sb[1], sb[2], sb[3]);
        }
    }
    __syncthreads();

    // ============ L2 fused with da2 = W3[f]*sigmoid(a2) -> bufA ============
    {
        const ulonglong2 bv = *(const ulonglong2*)(b2 + f4);
        #pragma unroll
        for (int i = 0; i < 4; i++) { acc[i][0] = bv.x; acc[i][1] = bv.y; }
        mmv(acc, bufB, HID, W2, HID, f4, s0);
        const float4 w3v = *(const float4*)(W3 + f4);
        float wv[4] = {w3v.x, w3v.y, w3v.z, w3v.w};
        #pragma unroll
        for (int i = 0; i < 4; i++) {
            float2 a01 = upk(acc[i][0]), a23 = upk(acc[i][1]);
            float av[4] = {a01.x, a01.y, a23.x, a23.y};
            float db[4];
            #pragma unroll
            for (int j = 0; j < 4; j++) {
                float a = av[j];
                float e = expf(-fabsf(a));
                float t = 1.0f / (1.0f + e);
                float sgv = (a >= 0.f) ? t : e * t;
                db[j] = wv[j] * sgv;
            }
            *(float4*)(bufA + (s0 + i) * HID + f4) = make_float4(db[0], db[1], db[2], db[3]);
        }
    }
    __syncthreads();

    // ============ B1: dh1 = da2 @ W2^T ; da1 = dh1*sig1 -> bufB ============
    {
        #pragma unroll
        for (int i = 0; i < 4; i++) { acc[i][0] = 0ull; acc[i][1] = 0ull; }
        mmv(acc, bufA, HID, g_W2T, HID, f4, s0);
        #pragma unroll
        for (int i = 0; i < 4; i++) {
            int o = (s0 + i) * HID + f4;
            float4 sg4 = *(const float4*)(sig1 + o);
            float2 a01 = upk(acc[i][0]), a23 = upk(acc[i][1]);
            *(float4*)(bufB + o) = make_float4(a01.x * sg4.x, a01.y * sg4.y,
                                               a23.x * sg4.z, a23.y * sg4.w);
        }
    }
    __syncthreads();

    // ============ B2: dh0 = da1 @ W1^T ; da0 = dh0*sig0 -> bufA ============
    {
        #pragma unroll
        for (int i = 0; i < 4; i++) { acc[i][0] = 0ull; acc[i][1] = 0ull; }
        mmv(acc, bufB, HID, g_W1T, HID, f4, s0);
        #pragma unroll
        for (int i = 0; i < 4; i++) {
            int o = (s0 + i) * HID + f4;
            float4 sg4 = *(const float4*)(sig0 + o);
            float2 a01 = upk(acc[i][0]), a23 = upk(acc[i][1]);
            *(float4*)(bufA + o) = make_float4(a01.x * sg4.x, a01.y * sg4.y,
                                               a23.x * sg4.z, a23.y * sg4.w);
        }
    }
    __syncthreads();

    // ============ B3: g = dV/dr = da0 @ W0^T (256 -> 64) -> gbuf ============
    // warp w handles samples 2w, 2w+1; lane m' covers features 2m', 2m'+1.
    {
        const int mp = (tid & 31) * 2;
        const int sb = (tid >> 5) * 2;
        ull a2[2] = {0ull, 0ull};
        #pragma unroll 2
        for (int k4 = 0; k4 < HID; k4 += 4) {
            float4 h0 = *(const float4*)(bufA + sb * HID + k4);
            float4 h1 = *(const float4*)(bufA + (sb + 1) * HID + k4);
            #pragma unroll
            for (int kk = 0; kk < 4; kk++) {
                ull wv = *(const ull*)(g_W0T + (k4 + kk) * INF + mp);
                a2[0] = ff2(pk2(fcomp(h0, kk)), wv, a2[0]);
                a2[1] = ff2(pk2(fcomp(h1, kk)), wv, a2[1]);
            }
        }
        float2 g0 = upk(a2[0]), g1 = upk(a2[1]);
        gbuf[sb * GST + mp]           = g0.x;
        gbuf[sb * GST + mp + 1]       = g0.y;
        gbuf[(sb + 1) * GST + mp]     = g1.x;
        gbuf[(sb + 1) * GST + mp + 1] = g1.y;
    }
    __syncthreads();

    // ============ constraint solve: 1 thread / sample ============
    // A = [[0,G],[-G,S]] with G = E^T M^-1 E tridiagonal SPD (32x32),
    // S tridiagonal antisymmetric. Two Thomas solves.
    float* scr = sig0;  // sig0+sig1 (16384 floats) free now
    float* Ex  = scr + 0  * NND * TB;
    float* Ey  = scr + 1  * NND * TB;
    float* Edx = scr + 2  * NND * TB;
    float* Edy = scr + 3  * NND * TB;
    float* Vx  = scr + 4  * NND * TB;
    float* Vy  = scr + 5  * NND * TB;
    float* Dd  = scr + 6  * NND * TB;
    float* Du  = scr + 7  * NND * TB;
    float* Dl  = scr + 8  * NND * TB;
    float* So  = scr + 9  * NND * TB;
    float* R0  = scr + 10 * NND * TB;   // b0 -> x1
    float* R1  = scr + 11 * NND * TB;   // b1 -> y -> x0

    if (tid < TB) {
        const int s = tid;
        const float* zr = zbuf + s * ZST;

        // build E_c, Edot_c, v  (E_0 = 2 r_0; E_c = 2(r_{c-1}-r_c))
        {
            float prx = zr[0], pry = zr[1];
            float im  = invm[0];
            float pvx = zr[64] * im, pvy = zr[65] * im;
            Ex[s]  = 2.f * prx;  Ey[s]  = 2.f * pry;
            Edx[s] = 2.f * pvx;  Edy[s] = 2.f * pvy;
            Vx[s] = pvx; Vy[s] = pvy;
            for (int c = 1; c < NND; c++) {
                float rx = zr[2*c], ry = zr[2*c+1];
                float imc = invm[c];
                float vx = zr[64 + 2*c] * imc, vy = zr[65 + 2*c] * imc;
                Ex[c*TB+s]  = 2.f*(prx - rx);  Ey[c*TB+s]  = 2.f*(pry - ry);
                Edx[c*TB+s] = 2.f*(pvx - vx);  Edy[c*TB+s] = 2.f*(pvy - vy);
                Vx[c*TB+s] = vx; Vy[c*TB+s] = vy;
                prx = rx; pry = ry; pvx = vx; pvy = vy;
            }
        }
        // tridiagonal G (Dd diag, Du upper), S offdiag (So), rhs b0 (R0), b1 (R1)
        {
            float e0x = Ex[s],  e0y = Ey[s];
            float d0x = Edx[s], d0y = Edy[s];
            float v0x = Vx[s],  v0y = Vy[s];
            float im0 = invm[0];
            float e1x = Ex[TB+s],  e1y = Ey[TB+s];
            float d1x = Edx[TB+s], d1y = Edy[TB+s];
            Dd[s] = im0 * (e0x*e0x + e0y*e0y);
            Du[s] = im0 * (e0x*e1x + e0y*e1y);
            So[s] = im0 * (d0x*e1x + d0y*e1y - d1x*e0x - d1y*e0y);
            R0[s] = e0x*v0x + e0y*v0y;
            float g0x = gbuf[s*GST + 0], g0y = gbuf[s*GST + 1];
            R1[s] = d0x*v0x + d0y*v0y - im0*(e0x*g0x + e0y*g0y);
            for (int c = 1; c < NND; c++) {
                float ecx = Ex[c*TB+s],  ecy = Ey[c*TB+s];
                float dcx = Edx[c*TB+s], dcy = Edy[c*TB+s];
                float imc = invm[c], imp = invm[c-1];
                Dd[c*TB+s] = (imp + imc) * (ecx*ecx + ecy*ecy);
                R0[c*TB+s] = 0.5f * (ecx*dcx + ecy*dcy);
                float gpx = gbuf[s*GST + 2*(c-1)], gpy = gbuf[s*GST + 2*(c-1)+1];
                float gcx = gbuf[s*GST + 2*c],     gcy = gbuf[s*GST + 2*c+1];
                R1[c*TB+s] = 0.5f*(dcx*dcx + dcy*dcy)
                           - (ecx*(imp*gpx - imc*gcx) + ecy*(imp*gpy - imc*gcy));
                if (c < NND - 1) {
                    float enx = Ex[(c+1)*TB+s],  eny = Ey[(c+1)*TB+s];
                    float dnx = Edx[(c+1)*TB+s], dny = Edy[(c+1)*TB+s];
                    Du[c*TB+s] = -imc * (ecx*enx + ecy*eny);
                    So[c*TB+s] =  imc * (dnx*ecx + dny*ecy - dcx*enx - dcy*eny);
                }
            }
        }
        // Thomas factorization of G
        for (int c = 1; c < NND; c++) {
            float l = Du[(c-1)*TB+s] / Dd[(c-1)*TB+s];
            Dl[c*TB+s] = l;
            Dd[c*TB+s] = Dd[c*TB+s] - l * Du[(c-1)*TB+s];
        }
        // solve G x1 = b0 (in place in R0)
        for (int c = 1; c < NND; c++)
            R0[c*TB+s] -= Dl[c*TB+s] * R0[(c-1)*TB+s];
        R0[(NND-1)*TB+s] /= Dd[(NND-1)*TB+s];
        for (int c = NND - 2; c >= 0; c--)
            R0[c*TB+s] = (R0[c*TB+s] - Du[c*TB+s] * R0[(c+1)*TB+s]) / Dd[c*TB+s];
        // y = S x1 - b1 (into R1)
        R1[s] = So[s] * R0[TB+s] - R1[s];
        for (int c = 1; c < NND - 1; c++)
            R1[c*TB+s] = So[c*TB+s]*R0[(c+1)*TB+s] - So[(c-1)*TB+s]*R0[(c-1)*TB+s] - R1[c*TB+s];
        R1[(NND-1)*TB+s] = -So[(NND-2)*TB+s]*R0[(NND-2)*TB+s] - R1[(NND-1)*TB+s];
        // solve G x0 = y (in place in R1)
        for (int c = 1; c < NND; c++)
            R1[c*TB+s] -= Dl[c*TB+s] * R1[(c-1)*TB+s];
        R1[(NND-1)*TB+s] /= Dd[(NND-1)*TB+s];
        for (int c = NND - 2; c >= 0; c--)
            R1[c*TB+s] = (R1[c*TB+s] - Du[c*TB+s]*R1[(c+1)*TB+s]) / Dd[c*TB+s];

        // output: out_r = v - M^-1 (E x1);  out_p = -g + (E x0) + (Edot x1)
        float* st = bufB + s * SST;
        for (int i = 0; i < NND; i++) {
            float eix = Ex[i*TB+s],  eiy = Ey[i*TB+s];
            float dix = Edx[i*TB+s], diy = Edy[i*TB+s];
            float x1i = R0[i*TB+s],  x0i = R1[i*TB+s];
            float p1x, p1y, p0x, p0y, pdx, pdy;
            if (i == 0) {
                float enx = Ex[TB+s],  eny = Ey[TB+s];
                float dnx = Edx[TB+s], dny = Edy[TB+s];
                float x1n = R0[TB+s],  x0n = R1[TB+s];
                p1x = eix*x1i + enx*x1n;  p1y = eiy*x1i + eny*x1n;
                p0x = eix*x0i + enx*x0n;  p0y = eiy*x0i + eny*x0n;
                pdx = dix*x1i + dnx*x1n;  pdy = diy*x1i + dny*x1n;
            } else if (i < NND - 1) {
                float enx = Ex[(i+1)*TB+s],  eny = Ey[(i+1)*TB+s];
                float dnx = Edx[(i+1)*TB+s], dny = Edy[(i+1)*TB+s];
                float x1n = R0[(i+1)*TB+s],  x0n = R1[(i+1)*TB+s];
                p1x = -eix*x1i + enx*x1n;  p1y = -eiy*x1i + eny*x1n;
                p0x = -eix*x0i + enx*x0n;  p0y = -eiy*x0i + eny*x0n;
                pdx = -dix*x1i + dnx*x1n;  pdy = -diy*x1i + dny*x1n;
            } else {
                p1x = -eix*x1i; p1y = -eiy*x1i;
                p0x = -eix*x0i; p0y = -eiy*x0i;
                pdx = -dix*x1i; pdy = -diy*x1i;
            }
            float imi = invm[i];
            st[2*i]     = Vx[i*TB+s] - imi * p1x;
            st[2*i + 1] = Vy[i*TB+s] - imi * p1y;
            float gx = gbuf[s*GST + 2*i], gy = gbuf[s*GST + 2*i + 1];
            st[64 + 2*i]     = -gx + p0x + pdx;
            st[64 + 2*i + 1] = -gy + p0y + pdy;
        }
    }
    __syncthreads();

    // coalesced store of staged output
    float* outg = out + (size_t)blk * TB * ZDIM;
    for (int i = tid; i < TB * ZDIM; i += NTHR)
        outg[i] = bufB[(i >> 7) * SST + (i & 127)];
}

extern "C" void kernel_launch(void* const* d_in, const int* in_sizes, int n_in,
                              void* d_out, int out_size)
{
    (void)in_sizes; (void)n_in; (void)out_size;
    const float* z  = (const float*)d_in[1];
    const float* mp = (const float*)d_in[2];
    const float* W0 = (const float*)d_in[3];
    const float* b0 = (const float*)d_in[4];
    const float* W1 = (const float*)d_in[5];
    const float* b1 = (const float*)d_in[6];
    const float* W2 = (const float*)d_in[7];
    const float* b2 = (const float*)d_in[8];
    const float* W3 = (const float*)d_in[9];
    float* out = (float*)d_out;

    transpose_k<<<(HID * HID + 255) / 256, 256>>>(W0, W1, W2);

    size_t smem = (size_t)(TB * ZST + 4 * TB * HID + TB * GST + 32) * sizeof(float);
    cudaFuncSetAttribute(chnn_kernel, cudaFuncAttributeMaxDynamicSharedMemorySize, (int)smem);
    chnn_kernel<<<NCTA, NTHR, smem>>>(z, mp, W0, b0, W1, b1, W2, b2, W3, out);
}